// round 10
// baseline (speedup 1.0000x reference)
#include <cuda_runtime.h>
#include <cuda_bf16.h>
#include <cstdint>

typedef __nv_bfloat16 bf16;

// Problem constants
#define S_  2048
#define B_  2
#define E_  1024
#define H_  16
#define D_  64
#define T_  2048

#define KC 32     // k elems per chunk
#define KP 40     // padded k stride (elems); 80B rows -> conflict-free ldmatrix

// ---------------------------------------------------------------------------
// Scratch (__device__ globals; no allocations allowed)
// ---------------------------------------------------------------------------
__device__ bf16 g_xh [4096L * 1024], g_xl [4096L * 1024];
__device__ bf16 g_wqh[1024L * 1024], g_wql[1024L * 1024];
__device__ bf16 g_wkh[1024L * 1024], g_wkl[1024L * 1024];
__device__ bf16 g_wvh[1024L * 1024], g_wvl[1024L * 1024];
__device__ bf16 g_woh[1024L * 1024], g_wol[1024L * 1024];
__device__ bf16 g_qh [4096L * 1024], g_ql [4096L * 1024];
__device__ bf16 g_kh [4096L * 1024], g_kl [4096L * 1024];
__device__ bf16 g_vh [4096L * 1024], g_vl [4096L * 1024];
__device__ bf16 g_vth[2048L * 2048], g_vtl[2048L * 2048];  // V^T per bz: row = bz*64+d
__device__ bf16 g_oh [4096L * 1024], g_ol [4096L * 1024];
__device__ float g_e  [2048L * 2 * 16 * 2048];             // exp(scores) fp32 (s,b,h,t)
__device__ float g_invz[2048L * 2 * 2048];                 // 1/Z  layout [s][b][t]

// ---------------------------------------------------------------------------
// Helpers
// ---------------------------------------------------------------------------
__device__ __forceinline__ uint32_t smem_u32(const void* p) {
    uint32_t a;
    asm("{ .reg .u64 t; cvta.to.shared.u64 t, %1; cvt.u32.u64 %0, t; }"
        : "=r"(a) : "l"(p));
    return a;
}

__device__ __forceinline__ void mma16816(float* c, uint32_t a0, uint32_t a1,
                                         uint32_t a2, uint32_t a3,
                                         uint32_t b0, uint32_t b1)
{
    asm volatile(
        "mma.sync.aligned.m16n8k16.row.col.f32.bf16.bf16.f32 "
        "{%0,%1,%2,%3}, {%4,%5,%6,%7}, {%8,%9}, {%0,%1,%2,%3};"
        : "+f"(c[0]), "+f"(c[1]), "+f"(c[2]), "+f"(c[3])
        : "r"(a0), "r"(a1), "r"(a2), "r"(a3), "r"(b0), "r"(b1));
}

__device__ __forceinline__ void ldsm4(uint32_t& d0, uint32_t& d1, uint32_t& d2,
                                      uint32_t& d3, uint32_t a)
{
    asm volatile("ldmatrix.sync.aligned.m8n8.x4.shared.b16 {%0,%1,%2,%3}, [%4];"
                 : "=r"(d0), "=r"(d1), "=r"(d2), "=r"(d3) : "r"(a));
}

__device__ __forceinline__ void cpa16(uint32_t dst, const void* src) {
    asm volatile("cp.async.cg.shared.global [%0], [%1], 16;" :: "r"(dst), "l"(src));
}
#define CP_COMMIT() asm volatile("cp.async.commit_group;" ::: "memory")
#define CP_WAIT(n)  asm volatile("cp.async.wait_group %0;" :: "n"(n) : "memory")

__device__ __forceinline__ void split2(float x, float y, uint32_t& h, uint32_t& l)
{
    bf16 hx = __float2bfloat16(x), hy = __float2bfloat16(y);
    bf16 lx = __float2bfloat16(x - __bfloat162float(hx));
    bf16 ly = __float2bfloat16(y - __bfloat162float(hy));
    h = ((uint32_t)__bfloat16_as_ushort(hy) << 16) | __bfloat16_as_ushort(hx);
    l = ((uint32_t)__bfloat16_as_ushort(ly) << 16) | __bfloat16_as_ushort(lx);
}

// ---------------------------------------------------------------------------
// Merged one-time fp32 -> bf16 hi/lo split (grid.y selects tensor)
// ---------------------------------------------------------------------------
__global__ __launch_bounds__(256)
void split_all(const float* __restrict__ x,
               const float* __restrict__ Wq, const float* __restrict__ Wk,
               const float* __restrict__ Wv, const float* __restrict__ Wo)
{
    const int  y = blockIdx.y;
    const float* s;
    bf16 *hi, *lo;
    int n4;
    switch (y) {
        case 0: s = Wq; hi = g_wqh; lo = g_wql; n4 = 262144; break;
        case 1: s = Wk; hi = g_wkh; lo = g_wkl; n4 = 262144; break;
        case 2: s = Wv; hi = g_wvh; lo = g_wvl; n4 = 262144; break;
        case 3: s = Wo; hi = g_woh; lo = g_wol; n4 = 262144; break;
        default: s = x; hi = g_xh; lo = g_xl; n4 = 1048576; break;
    }
    int i = blockIdx.x * blockDim.x + threadIdx.x;
    if (i >= n4) return;
    float4 v = *(const float4*)(s + (long)i * 4);
    uint32_t h0, l0, h1, l1;
    split2(v.x, v.y, h0, l0);
    split2(v.z, v.w, h1, l1);
    *(uint2*)(hi + (long)i * 4) = make_uint2(h0, h1);
    *(uint2*)(lo + (long)i * 4) = make_uint2(l0, l1);
}

// ---------------------------------------------------------------------------
// V^T precompute: g_vt[bz*64 + d][t] = g_v[t*2048 + bz*64 + d]
// ---------------------------------------------------------------------------
__global__ __launch_bounds__(256)
void transpose_v()
{
    __shared__ bf16 th[32 * 68], tl[32 * 68];
    const int bz = blockIdx.y;
    const int t0 = blockIdx.x * 32;
    const int tid = threadIdx.x;

#pragma unroll
    for (int i = 0; i < 2; i++) {
        int id = tid + i * 256;
        int t  = id >> 4;
        int d  = (id & 15) * 4;
        long g = (long)(t0 + t) * 2048 + (long)bz * 64 + d;
        *(uint2*)&th[t * 68 + d] = *(const uint2*)&g_vh[g];
        *(uint2*)&tl[t * 68 + d] = *(const uint2*)&g_vl[g];
    }
    __syncthreads();
#pragma unroll
    for (int i = 0; i < 2; i++) {
        int id = tid + i * 256;
        int d  = id >> 3;
        int t  = (id & 7) * 4;
        uint32_t h0 = ((uint32_t)__bfloat16_as_ushort(th[(t + 1) * 68 + d]) << 16)
                    | __bfloat16_as_ushort(th[(t + 0) * 68 + d]);
        uint32_t h1 = ((uint32_t)__bfloat16_as_ushort(th[(t + 3) * 68 + d]) << 16)
                    | __bfloat16_as_ushort(th[(t + 2) * 68 + d]);
        uint32_t l0 = ((uint32_t)__bfloat16_as_ushort(tl[(t + 1) * 68 + d]) << 16)
                    | __bfloat16_as_ushort(tl[(t + 0) * 68 + d]);
        uint32_t l1 = ((uint32_t)__bfloat16_as_ushort(tl[(t + 3) * 68 + d]) << 16)
                    | __bfloat16_as_ushort(tl[(t + 2) * 68 + d]);
        long o = (long)(bz * 64 + d) * 2048 + t0 + t;
        *(uint2*)&g_vth[o] = make_uint2(h0, h1);
        *(uint2*)&g_vtl[o] = make_uint2(l0, l1);
    }
}

// ---------------------------------------------------------------------------
// NT GEMM body: cp.async double-buffered, ldmatrix, split-bf16 fp32 emulation.
// Output: fp32 (Cf, optionally exp()) or split bf16 (Ch,Cl).
// Dynamic smem: 2 bufs x [Ah|Al|Bh|Bl] x 128*KP bf16 = 81920 B.
// ---------------------------------------------------------------------------
#define ARR_  10240u
#define BUF_  40960u

__device__ __forceinline__ void gemm_bf16_nt(
    const bf16* __restrict__ Ah, const bf16* __restrict__ Al, long lda,
    const bf16* __restrict__ Bh, const bf16* __restrict__ Bl, long ldb,
    const float* __restrict__ bias, int K, float alpha, int expOut,
    float* __restrict__ Cf, bf16* __restrict__ Ch, bf16* __restrict__ Cl,
    long ldc)
{
    extern __shared__ char smc[];
    const uint32_t sb = smem_u32(smc);
    const int tid = threadIdx.x, wid = tid >> 5, lane = tid & 31;
    const int wm = (wid >> 2) * 64, wn = (wid & 3) * 32;

    const uint32_t aoff = (((lane & 15) * KP) + ((lane >> 4) * 8)) * 2;
    const uint32_t boff = ((((lane & 7) + ((lane >> 4) << 3)) * KP)
                           + (((lane >> 3) & 1) * 8)) * 2;

    float acc[4][4][4];
#pragma unroll
    for (int i = 0; i < 4; i++)
#pragma unroll
        for (int j = 0; j < 4; j++)
#pragma unroll
            for (int r = 0; r < 4; r++) acc[i][j][r] = 0.0f;

    const int nchunks = K / KC;

    auto stage = [&](int b, int k0) {
        uint32_t base = sb + (uint32_t)b * BUF_;
#pragma unroll
        for (int i = 0; i < 2; i++) {
            int id  = tid + i * 256;
            int row = id >> 2;
            int c8  = (id & 3) * 8;
            uint32_t so = (uint32_t)(row * KP + c8) * 2;
            cpa16(base + so,            Ah + (long)row * lda + k0 + c8);
            cpa16(base + ARR_ + so,     Al + (long)row * lda + k0 + c8);
            cpa16(base + 2 * ARR_ + so, Bh + (long)row * ldb + k0 + c8);
            cpa16(base + 3 * ARR_ + so, Bl + (long)row * ldb + k0 + c8);
        }
    };

    stage(0, 0);
    CP_COMMIT();

    for (int c = 0; c < nchunks; c++) {
        const int cur = c & 1;
        if (c + 1 < nchunks) {
            stage(cur ^ 1, (c + 1) * KC);
            CP_COMMIT();
            CP_WAIT(1);
        } else {
            CP_WAIT(0);
        }
        __syncthreads();

        const uint32_t bufb = sb + (uint32_t)cur * BUF_;
        const uint32_t abh = bufb + (uint32_t)wm * KP * 2 + aoff;
        const uint32_t abl = abh + ARR_;
        const uint32_t bbh = bufb + 2 * ARR_ + (uint32_t)wn * KP * 2 + boff;
        const uint32_t bbl = bbh + ARR_;

#pragma unroll
        for (int kc = 0; kc < 2; kc++) {
            const uint32_t ko = kc * 32;
            uint32_t BH[8], BL[8];
            ldsm4(BH[0], BH[1], BH[2], BH[3], bbh + ko);
            ldsm4(BH[4], BH[5], BH[6], BH[7], bbh + 16 * KP * 2 + ko);
            ldsm4(BL[0], BL[1], BL[2], BL[3], bbl + ko);
            ldsm4(BL[4], BL[5], BL[6], BL[7], bbl + 16 * KP * 2 + ko);
#pragma unroll
            for (int mt = 0; mt < 4; mt++) {
                uint32_t a0, a1, a2, a3, l0, l1, l2, l3;
                ldsm4(a0, a1, a2, a3, abh + (uint32_t)mt * 16 * KP * 2 + ko);
                ldsm4(l0, l1, l2, l3, abl + (uint32_t)mt * 16 * KP * 2 + ko);
#pragma unroll
                for (int nt = 0; nt < 4; nt++) {
                    mma16816(acc[mt][nt], a0, a1, a2, a3, BH[2 * nt], BH[2 * nt + 1]);
                    mma16816(acc[mt][nt], a0, a1, a2, a3, BL[2 * nt], BL[2 * nt + 1]);
                    mma16816(acc[mt][nt], l0, l1, l2, l3, BH[2 * nt], BH[2 * nt + 1]);
                }
            }
        }
        __syncthreads();
    }

    const int lrow = lane >> 2;
#pragma unroll
    for (int mt = 0; mt < 4; mt++) {
        int row = wm + mt * 16 + lrow;
#pragma unroll
        for (int nt = 0; nt < 4; nt++) {
            int col = wn + nt * 8 + (lane & 3) * 2;
            float b0 = 0.f, b1 = 0.f;
            if (bias) { b0 = bias[col]; b1 = bias[col + 1]; }
            float y00 = acc[mt][nt][0] * alpha + b0;
            float y01 = acc[mt][nt][1] * alpha + b1;
            float y10 = acc[mt][nt][2] * alpha + b0;
            float y11 = acc[mt][nt][3] * alpha + b1;
            if (Cf) {
                if (expOut) {
                    y00 = __expf(y00); y01 = __expf(y01);
                    y10 = __expf(y10); y11 = __expf(y11);
                }
                *(float2*)(Cf + (long)row * ldc + col)       = make_float2(y00, y01);
                *(float2*)(Cf + (long)(row + 8) * ldc + col) = make_float2(y10, y11);
            } else {
                uint32_t h, l;
                split2(y00, y01, h, l);
                *(uint32_t*)&Ch[(long)row * ldc + col] = h;
                *(uint32_t*)&Cl[(long)row * ldc + col] = l;
                split2(y10, y11, h, l);
                *(uint32_t*)&Ch[(long)(row + 8) * ldc + col] = h;
                *(uint32_t*)&Cl[(long)(row + 8) * ldc + col] = l;
            }
        }
    }
}

// ---------------------------------------------------------------------------
// Wrappers (dynamic smem = 81920)
// ---------------------------------------------------------------------------
__global__ __launch_bounds__(256)
void gemm_qkv(const float* __restrict__ bq, const float* __restrict__ bk,
              const float* __restrict__ bv)
{
    const long bm = blockIdx.y, bn = blockIdx.x;
    const int  z  = blockIdx.z;
    const bf16* Wh = (z == 0) ? g_wqh : (z == 1) ? g_wkh : g_wvh;
    const bf16* Wl = (z == 0) ? g_wql : (z == 1) ? g_wkl : g_wvl;
    const float* b = (z == 0) ? bq   : (z == 1) ? bk   : bv;
    bf16* Ch = (z == 0) ? g_qh : (z == 1) ? g_kh : g_vh;
    bf16* Cl = (z == 0) ? g_ql : (z == 1) ? g_kl : g_vl;
    gemm_bf16_nt(g_xh + bm * 128 * 1024, g_xl + bm * 128 * 1024, 1024,
                 Wh + bn * 128 * 1024, Wl + bn * 128 * 1024, 1024,
                 b + bn * 128, 1024, 1.0f, 0,
                 nullptr,
                 Ch + bm * 128 * 1024 + bn * 128,
                 Cl + bm * 128 * 1024 + bn * 128, 1024);
}

// scores -> e = exp(score) fp32
__global__ __launch_bounds__(256)
void gemm_sc()
{
    const long bm = blockIdx.y, bn = blockIdx.x, bz = blockIdx.z;  // bz = b*16+h
    gemm_bf16_nt(g_qh + bz * 64 + bm * 128 * 2048,
                 g_ql + bz * 64 + bm * 128 * 2048, 2048,
                 g_kh + bz * 64 + bn * 128 * 2048,
                 g_kl + bz * 64 + bn * 128 * 2048, 2048,
                 nullptr, 64, 0.125f, 1,
                 g_e + bz * 2048 + bm * 128 * 65536 + bn * 128,
                 nullptr, nullptr, 65536);
}

__global__ __launch_bounds__(256)
void gemm_proj(const float* __restrict__ bias, float* __restrict__ out)
{
    const long bm = blockIdx.y, bn = blockIdx.x;
    gemm_bf16_nt(g_oh + bm * 128 * 1024, g_ol + bm * 128 * 1024, 1024,
                 g_woh + bn * 128 * 1024, g_wol + bn * 128 * 1024, 1024,
                 bias + bn * 128, 1024, 1.0f, 0,
                 out + bm * 128 * 1024 + bn * 128,
                 nullptr, nullptr, 1024);
}

// ---------------------------------------------------------------------------
// invZ[s,b,t] = 1 / sum_h e[s,b,h,t]
// ---------------------------------------------------------------------------
__global__ __launch_bounds__(256)
void denom_invz()
{
    long idx = (long)blockIdx.x * blockDim.x + threadIdx.x;   // 2,097,152
    int  t = (int)(idx & 511) * 4;
    long r = idx >> 9;
    int  b = (int)(r & 1);
    long s = r >> 1;
    long base = s * 65536 + (long)b * 32768 + t;

    float4 z = make_float4(0.f, 0.f, 0.f, 0.f);
#pragma unroll
    for (int h = 0; h < H_; h++) {
        float4 e = *(const float4*)&g_e[base + (long)h * 2048];
        z.x += e.x; z.y += e.y; z.z += e.z; z.w += e.w;
    }
    float4 iz = make_float4(1.f / z.x, 1.f / z.y, 1.f / z.z, 1.f / z.w);
    *(float4*)&g_invz[s * 4096 + (long)b * 2048 + t] = iz;
}

// ---------------------------------------------------------------------------
// AV GEMM with fused normalization: stages raw e (fp32), converts
// attn = e*invZ -> split bf16 in smem, then ldmatrix/MMA vs V^T.
// smem: 2 x [vh(5120)|vl(5120)|e(16384)] + attn hi(10240)+lo(10240) = 73728 B.
// ---------------------------------------------------------------------------
#define AVB_   26624u    // per-buffer: vh 5120 | vl 5120 | e 16384
#define AV_AT_ 53248u    // attn region offset

__global__ __launch_bounds__(256)
void gemm_av()
{
    extern __shared__ char smc[];
    const uint32_t sb = smem_u32(smc);
    const int tid = threadIdx.x, wid = tid >> 5, lane = tid & 31;
    const int wm = (wid >> 2) * 64, wn = (wid & 3) * 16;

    const int  bz = blockIdx.z;          // b*16 + h
    const int  b  = bz >> 4;
    const long m0 = blockIdx.y * 128;    // s-tile

    const float* scp = g_e + (long)bz * 2048;          // + s*65536 + t
    const bf16* Bhp = g_vth + (long)bz * 64 * 2048;
    const bf16* Blp = g_vtl + (long)bz * 64 * 2048;

    const uint32_t aoff = (((lane & 15) * KP) + ((lane >> 4) * 8)) * 2;
    const uint32_t boff = ((((lane & 7) + ((lane >> 4) << 3)) * KP)
                           + (((lane >> 3) & 1) * 8)) * 2;

    float acc[4][2][4];
#pragma unroll
    for (int i = 0; i < 4; i++)
#pragma unroll
        for (int j = 0; j < 2; j++)
#pragma unroll
            for (int r = 0; r < 4; r++) acc[i][j][r] = 0.0f;

    auto stage = [&](int bb, int k0) {
        uint32_t base = sb + (uint32_t)bb * AVB_;
        {   // V^T: 64 rows x 32 t, hi & lo
            int row = tid >> 2;
            int c8  = (tid & 3) * 8;
            uint32_t so = (uint32_t)(row * KP + c8) * 2;
            long gb = (long)row * 2048 + k0 + c8;
            cpa16(base + so,         Bhp + gb);
            cpa16(base + 5120u + so, Blp + gb);
        }
        // e raw: 128 rows x 32 floats
#pragma unroll
        for (int i = 0; i < 4; i++) {
            int id  = tid + i * 256;
            int row = id >> 3;
            int c4  = (id & 7) * 4;
            uint32_t so = (uint32_t)(row * 32 + c4) * 4;
            cpa16(base + 10240u + so, scp + (m0 + row) * 65536 + k0 + c4);
        }
    };

    stage(0, 0);
    CP_COMMIT();

    const int nchunks = T_ / KC;   // 64
    for (int c = 0; c < nchunks; c++) {
        const int cur = c & 1;
        if (c + 1 < nchunks) {
            stage(cur ^ 1, (c + 1) * KC);
            CP_COMMIT();
            CP_WAIT(1);
        } else {
            CP_WAIT(0);
        }
        __syncthreads();

        // convert: attn = e * invZ -> split bf16 into attn region
        {
            const float* es = (const float*)(smc + cur * AVB_ + 10240u);
            char* ah = smc + AV_AT_;
            char* al = smc + AV_AT_ + 10240u;
            const int k0 = c * KC;
#pragma unroll
            for (int i = 0; i < 4; i++) {
                int id  = tid + i * 256;
                int row = id >> 3;
                int c4  = (id & 7) * 4;
                float4 e4 = *(const float4*)(es + row * 32 + c4);
                float4 iz = *(const float4*)&g_invz[(m0 + row) * 4096
                                                    + (long)b * 2048 + k0 + c4];
                float a0 = e4.x * iz.x, a1 = e4.y * iz.y;
                float a2 = e4.z * iz.z, a3 = e4.w * iz.w;
                uint32_t h0, l0, h1, l1;
                split2(a0, a1, h0, l0);
                split2(a2, a3, h1, l1);
                *(uint2*)(ah + (row * KP + c4) * 2) = make_uint2(h0, h1);
                *(uint2*)(al + (row * KP + c4) * 2) = make_uint2(l0, l1);
            }
        }
        __syncthreads();

        const uint32_t abh = sb + AV_AT_ + (uint32_t)wm * KP * 2 + aoff;
        const uint32_t abl = abh + 10240u;
        const uint32_t bbh = sb + (uint32_t)cur * AVB_ + (uint32_t)wn * KP * 2 + boff;
        const uint32_t bbl = bbh + 5120u;

#pragma unroll
        for (int kc = 0; kc < 2; kc++) {
            const uint32_t ko = kc * 32;
            uint32_t BH[4], BL[4];
            ldsm4(BH[0], BH[1], BH[2], BH[3], bbh + ko);
            ldsm4(BL[0], BL[1], BL[2], BL[3], bbl + ko);
#pragma unroll
            for (int mt = 0; mt < 4; mt++) {
                uint32_t a0, a1, a2, a3, l0, l1, l2, l3;
                ldsm4(a0, a1, a2, a3, abh + (uint32_t)mt * 16 * KP * 2 + ko);
                ldsm4(l0, l1, l2, l3, abl + (uint32_t)mt * 16 * KP * 2 + ko);
#pragma unroll
                for (int nt = 0; nt < 2; nt++) {
                    mma16816(acc[mt][nt], a0, a1, a2, a3, BH[2 * nt], BH[2 * nt + 1]);
                    mma16816(acc[mt][nt], a0, a1, a2, a3, BL[2 * nt], BL[2 * nt + 1]);
                    mma16816(acc[mt][nt], l0, l1, l2, l3, BH[2 * nt], BH[2 * nt + 1]);
                }
            }
        }
        __syncthreads();
    }

    // epilogue: split to oh/ol; o offset = s*2048 + 64*bz + d
    const int lrow = lane >> 2;
    const long obase = (long)bz * 64;
#pragma unroll
    for (int mt = 0; mt < 4; mt++) {
        long s = m0 + wm + mt * 16 + lrow;
#pragma unroll
        for (int nt = 0; nt < 2; nt++) {
            int col = wn + nt * 8 + (lane & 3) * 2;
            uint32_t h, l;
            split2(acc[mt][nt][0], acc[mt][nt][1], h, l);
            *(uint32_t*)&g_oh[s * 2048 + obase + col] = h;
            *(uint32_t*)&g_ol[s * 2048 + obase + col] = l;
            split2(acc[mt][nt][2], acc[mt][nt][3], h, l);
            *(uint32_t*)&g_oh[(s + 8) * 2048 + obase + col] = h;
            *(uint32_t*)&g_ol[(s + 8) * 2048 + obase + col] = l;
        }
    }
}

// ---------------------------------------------------------------------------
// Launch
// ---------------------------------------------------------------------------
extern "C" void kernel_launch(void* const* d_in, const int* in_sizes, int n_in,
                              void* d_out, int out_size)
{
    const float* x  = (const float*)d_in[0];
    const float* Wq = (const float*)d_in[1];
    const float* bq = (const float*)d_in[2];
    const float* Wk = (const float*)d_in[3];
    const float* bk = (const float*)d_in[4];
    const float* Wv = (const float*)d_in[5];
    const float* bv = (const float*)d_in[6];
    const float* Wo = (const float*)d_in[7];
    const float* bo = (const float*)d_in[8];
    float* out = (float*)d_out;

    cudaFuncSetAttribute(gemm_qkv,  cudaFuncAttributeMaxDynamicSharedMemorySize, 81920);
    cudaFuncSetAttribute(gemm_sc,   cudaFuncAttributeMaxDynamicSharedMemorySize, 81920);
    cudaFuncSetAttribute(gemm_proj, cudaFuncAttributeMaxDynamicSharedMemorySize, 81920);
    cudaFuncSetAttribute(gemm_av,   cudaFuncAttributeMaxDynamicSharedMemorySize, 73728);

    // 0. one-time splits (merged)
    split_all<<<dim3(4096, 5), 256>>>(x, Wq, Wk, Wv, Wo);

    // 1. Fused Q/K/V projections
    gemm_qkv<<<dim3(8, 32, 3), 256, 81920>>>(bq, bk, bv);

    // 2. V^T precompute
    transpose_v<<<dim3(64, 32), 256>>>();

    // 3. e = exp(scores)
    gemm_sc<<<dim3(16, 16, 32), 256, 81920>>>();

    // 4. invZ = 1 / sum_h e
    denom_invz<<<8192, 256>>>();

    // 5. O = (e*invZ) @ V^T   (normalization fused into staging)
    gemm_av<<<dim3(1, 16, 32), 256, 73728>>>();

    // 6. out projection
    gemm_proj<<<dim3(8, 32, 1), 256, 81920>>>(bo, out);
}